// round 17
// baseline (speedup 1.0000x reference)
#include <cuda_runtime.h>
#include <cuda_fp16.h>
#include <math.h>
#include <stdint.h>

// Problem constants
#define BB    2
#define TT    2048
#define CC    512
#define HH    8
#define DD    64
#define C3    1536
#define KSEL  4
#define GAMMA_F 2.5f
#define RHO_F   0.085f
#define TAUCLIP 5.0f
#define NROW  (BB*TT)       // 4096
#define KTOT  512

typedef unsigned long long ull;

// ---------------- scratch (device globals) ---------------------------------
__device__ float g_qkv[(size_t)NROW * C3];        // 24 MB fp32
__device__ __half g_x_h[(size_t)NROW * KTOT];     // x (fp16)
__device__ __half g_wqt[(size_t)C3 * KTOT];       // Wqkv^T fp16
__device__ __half g_wpt[(size_t)CC * KTOT];       // Wproj^T fp16
__device__ __half g_ao[(size_t)NROW * KTOT];      // attn_out fp16
__device__ ull    g_topkey[NROW * KSEL];          // packed (val,~idx) keys
__device__ float  g_rowsum[NROW];

// ===================== helpers ==============================================
__device__ __forceinline__ uint32_t smem_u32(const void* p) {
    uint32_t a;
    asm("{ .reg .u64 t; cvta.to.shared.u64 t, %1; cvt.u32.u64 %0, t; }" : "=r"(a) : "l"(p));
    return a;
}
__device__ __forceinline__ void ldsm_x4(uint32_t& r0, uint32_t& r1, uint32_t& r2, uint32_t& r3,
                                        uint32_t addr) {
    asm volatile("ldmatrix.sync.aligned.m8n8.x4.shared.b16 {%0,%1,%2,%3}, [%4];"
                 : "=r"(r0), "=r"(r1), "=r"(r2), "=r"(r3) : "r"(addr));
}
__device__ __forceinline__ void mma_fp16(float* d, const uint32_t* a, uint32_t b0, uint32_t b1) {
    asm("mma.sync.aligned.m16n8k16.row.col.f32.f16.f16.f32 "
        "{%0,%1,%2,%3}, {%4,%5,%6,%7}, {%8,%9}, {%0,%1,%2,%3};"
        : "+f"(d[0]), "+f"(d[1]), "+f"(d[2]), "+f"(d[3])
        : "r"(a[0]), "r"(a[1]), "r"(a[2]), "r"(a[3]), "r"(b0), "r"(b1));
}
__device__ __forceinline__ ull warp_max_key(ull h) {
    unsigned hi = (unsigned)(h >> 32);
    unsigned mhi = __reduce_max_sync(0xffffffffu, hi);
    unsigned lo = (hi == mhi) ? (unsigned)h : 0u;
    unsigned mlo = __reduce_max_sync(0xffffffffu, lo);
    return ((ull)mhi << 32) | mlo;
}

// ===================== fused operand prep ===================================
__device__ __forceinline__ void transp_tile(const float* __restrict__ W,
                                            __half* __restrict__ out,
                                            int n0, int k0, int N, int tid) {
    __shared__ float tile[32][33];
    int tx = tid & 31, ty = tid >> 5;
    #pragma unroll
    for (int i = 0; i < 32; i += 8)
        tile[ty + i][tx] = W[(size_t)(k0 + ty + i) * N + n0 + tx];
    __syncthreads();
    #pragma unroll
    for (int i = 0; i < 32; i += 8)
        out[(size_t)(n0 + ty + i) * KTOT + k0 + tx] = __float2half(tile[tx][ty + i]);
}

__global__ void prep_fused(const float* __restrict__ x, __half* __restrict__ xh,
                           const float* __restrict__ Wq, __half* __restrict__ wqt,
                           const float* __restrict__ Wp, __half* __restrict__ wpt) {
    const int bid = blockIdx.x;
    const int tid = threadIdx.x;
    if (bid < 2048) {
        int i = bid * 256 + tid;
        float4 v = reinterpret_cast<const float4*>(x)[i];
        reinterpret_cast<__half2*>(xh)[i * 2]     = __floats2half2_rn(v.x, v.y);
        reinterpret_cast<__half2*>(xh)[i * 2 + 1] = __floats2half2_rn(v.z, v.w);
    } else if (bid < 2048 + 768) {
        int t = bid - 2048;
        transp_tile(Wq, wqt, (t % 48) * 32, (t / 48) * 32, C3, tid);
    } else {
        int t = bid - 2816;
        transp_tile(Wp, wpt, (t % 16) * 32, (t / 16) * 32, CC, tid);
    }
}

// ===================== K64 / 2-stage / swizzled GEMM core ===================
// BM=64, BN=BNG*32 per warp-pair (BNG n16-groups per warp), 8 warps 4m x 2n.
#define A64_TILE 8192                // 64 rows x 128 B
#define G64_NCH 8

template<int BNG>
__device__ __forceinline__ void g64_load(
    uint32_t sm_base, int stage, int c, int m0, int n0, int tid,
    const __half* __restrict__ Ah, const __half* __restrict__ Bh)
{
    constexpr int BT = BNG * 4096;               // B tile bytes
    constexpr int STG = A64_TILE + BT;
    if (c < G64_NCH) {
        uint32_t sbase = sm_base + stage * STG;
        const int k0 = c * 64;
        #pragma unroll
        for (int i = 0; i < 2; i++) {
            int u = tid + i * 256;
            int r = u >> 3, cu = u & 7;
            const void* gp = Ah + (size_t)(m0 + r) * KTOT + k0 + cu * 8;
            uint32_t dst = sbase + r * 128 + ((cu ^ (r & 7)) << 4);
            asm volatile("cp.async.cg.shared.global [%0], [%1], 16;" :: "r"(dst), "l"(gp));
        }
        #pragma unroll
        for (int i = 0; i < BNG; i++) {
            int u = tid + i * 256;
            int r = u >> 3, cu = u & 7;
            const void* gp = Bh + (size_t)(n0 + r) * KTOT + k0 + cu * 8;
            uint32_t dst = sbase + A64_TILE + r * 128 + ((cu ^ (r & 7)) << 4);
            asm volatile("cp.async.cg.shared.global [%0], [%1], 16;" :: "r"(dst), "l"(gp));
        }
    }
    asm volatile("cp.async.commit_group;" ::: "memory");
}

template<int BNG>
__device__ __forceinline__ void gemm64_body(
    uint32_t sm_base, int m0, int n0, int tid,
    const __half* __restrict__ Ah, const __half* __restrict__ Bh,
    const float* __restrict__ bias, float* __restrict__ Cout, int N_out)
{
    constexpr int BT = BNG * 4096;
    constexpr int STG = A64_TILE + BT;
    const int wid = tid >> 5, lane = tid & 31;
    const int wm = wid >> 1, wn = wid & 1;

    float acc[2 * BNG][4];
    #pragma unroll
    for (int j = 0; j < 2 * BNG; j++)
        #pragma unroll
        for (int l = 0; l < 4; l++) acc[j][l] = 0.f;

    g64_load<BNG>(sm_base, 0, 0, m0, n0, tid, Ah, Bh);
    g64_load<BNG>(sm_base, 1, 1, m0, n0, tid, Ah, Bh);

    const int lrow = lane & 15;
    const int lu8 = (lane >> 4);

    for (int c = 0; c < G64_NCH; c++) {
        asm volatile("cp.async.wait_group 1;" ::: "memory");
        __syncthreads();
        const uint32_t stg = sm_base + (c & 1) * STG;

        #pragma unroll
        for (int kk = 0; kk < 4; kk++) {
            const int ubase = kk * 2 + lu8;
            uint32_t ah[4], bh[BNG][4];
            {
                int r = wm * 16 + lrow;
                uint32_t ra = stg + r * 128 + ((ubase ^ (r & 7)) << 4);
                ldsm_x4(ah[0], ah[1], ah[2], ah[3], ra);
            }
            #pragma unroll
            for (int jn = 0; jn < BNG; jn++) {
                int r = wn * (16 * BNG) + jn * 16 + lrow;
                uint32_t rb = stg + A64_TILE + r * 128 + ((ubase ^ (r & 7)) << 4);
                ldsm_x4(bh[jn][0], bh[jn][1], bh[jn][2], bh[jn][3], rb);
            }
            #pragma unroll
            for (int jn = 0; jn < BNG; jn++) {
                mma_fp16(acc[jn * 2],     ah, bh[jn][0], bh[jn][2]);
                mma_fp16(acc[jn * 2 + 1], ah, bh[jn][1], bh[jn][3]);
            }
        }
        __syncthreads();
        g64_load<BNG>(sm_base, c & 1, c + 2, m0, n0, tid, Ah, Bh);
    }

    {
        int rbase = m0 + wm * 16 + (lane >> 2);
        #pragma unroll
        for (int jf = 0; jf < 2 * BNG; jf++) {
            int col = n0 + wn * (16 * BNG) + jf * 8 + (lane & 3) * 2;
            float2 b2 = *reinterpret_cast<const float2*>(bias + col);
            float2 o0, o1;
            o0.x = acc[jf][0] + b2.x; o0.y = acc[jf][1] + b2.y;
            o1.x = acc[jf][2] + b2.x; o1.y = acc[jf][3] + b2.y;
            *reinterpret_cast<float2*>(Cout + (size_t)rbase * N_out + col) = o0;
            *reinterpret_cast<float2*>(Cout + (size_t)(rbase + 8) * N_out + col) = o1;
        }
    }
}

#define QKV_SMEM (2 * (A64_TILE + 4 * 4096))     // 49152
#define PROJ_SMEM (2 * (A64_TILE + 2 * 4096))    // 32768

__global__ __launch_bounds__(256, 3) void qkv_gemm64(
    const __half* __restrict__ Ah, const __half* __restrict__ Bh,
    const float* __restrict__ bias, float* __restrict__ Cout)
{
    extern __shared__ char smem[];
    gemm64_body<4>(smem_u32(smem), blockIdx.y * 64, blockIdx.x * 128, threadIdx.x,
                   Ah, Bh, bias, Cout, C3);
}

__global__ __launch_bounds__(256, 4) void proj_gemm64(
    const __half* __restrict__ Ah, const __half* __restrict__ Bh,
    const float* __restrict__ bias, float* __restrict__ Cout)
{
    extern __shared__ char smem[];
    gemm64_body<2>(smem_u32(smem), blockIdx.y * 64, blockIdx.x * 64, threadIdx.x,
                   Ah, Bh, bias, Cout, CC);
}

// ===================== topk kernel (tau only — runs on side stream) =========
__global__ __launch_bounds__(256) void topk_kernel(const float* __restrict__ tau) {
    const int row = blockIdx.x;
    const int tid = threadIdx.x;
    const int warp = tid >> 5, lane = tid & 31;

    __shared__ ull   swk[8 * 4];
    __shared__ float sred[8];

    const float4* tin = reinterpret_cast<const float4*>(tau + (size_t)row * TT);
    float4 v0 = tin[tid];
    float4 v1 = tin[tid + 256];
    float sum = (v0.x + v0.y) + (v0.z + v0.w) + (v1.x + v1.y) + (v1.z + v1.w);

    ull k0 = 0, k1 = 0, k2 = 0, k3 = 0;
    #define TK_INS(val, col) do { \
        ull key = ((ull)__float_as_uint(val) << 32) | (unsigned)(0x7FFFFFFF - (col)); \
        if (key > k3) { \
            if (key > k0)      { k3 = k2; k2 = k1; k1 = k0; k0 = key; } \
            else if (key > k1) { k3 = k2; k2 = k1; k1 = key; } \
            else if (key > k2) { k3 = k2; k2 = key; } \
            else               { k3 = key; } \
        } } while (0)
    {
        int c0 = tid * 4, c1 = (tid + 256) * 4;
        TK_INS(v0.x, c0);     TK_INS(v0.y, c0 + 1);
        TK_INS(v0.z, c0 + 2); TK_INS(v0.w, c0 + 3);
        TK_INS(v1.x, c1);     TK_INS(v1.y, c1 + 1);
        TK_INS(v1.z, c1 + 2); TK_INS(v1.w, c1 + 3);
    }
    #undef TK_INS

    ull t0, t1, t2, t3;
    {
        ull h = k0;
        #pragma unroll
        for (int r = 0; r < 4; r++) {
            ull m = warp_max_key(h);
            if (r == 0) t0 = m; else if (r == 1) t1 = m;
            else if (r == 2) t2 = m; else t3 = m;
            if (h == m) { h = k1; k1 = k2; k2 = k3; k3 = 0; }
        }
    }
    #pragma unroll
    for (int o = 16; o > 0; o >>= 1) sum += __shfl_xor_sync(0xffffffffu, sum, o);

    if (lane == 0) {
        swk[warp * 4 + 0] = t0; swk[warp * 4 + 1] = t1;
        swk[warp * 4 + 2] = t2; swk[warp * 4 + 3] = t3;
        sred[warp] = sum;
    }
    __syncthreads();

    if (warp == 0) {
        int src = lane & 7;
        ull l0 = swk[src * 4], l1 = swk[src * 4 + 1];
        ull l2 = swk[src * 4 + 2], l3 = swk[src * 4 + 3];
        ull m0, m1, m2, m3;
        {
            ull h = l0;
            #pragma unroll
            for (int r = 0; r < 4; r++) {
                ull m = warp_max_key(h);
                if (r == 0) m0 = m; else if (r == 1) m1 = m;
                else if (r == 2) m2 = m; else m3 = m;
                if (h == m) { h = l1; l1 = l2; l2 = l3; l3 = 0; }
            }
        }
        float rs = sred[src];
        rs += __shfl_xor_sync(0xffffffffu, rs, 1);
        rs += __shfl_xor_sync(0xffffffffu, rs, 2);
        rs += __shfl_xor_sync(0xffffffffu, rs, 4);
        if (lane < KSEL) {
            ull key = (lane == 0) ? m0 : (lane == 1) ? m1 : (lane == 2) ? m2 : m3;
            g_topkey[row * KSEL + lane] = key;
        }
        if (lane == 0) g_rowsum[row] = rs;
    }
}

// ===================== attention + tau_new (after QKV + topk) ===============
__global__ __launch_bounds__(256) void attn_tau(const float* __restrict__ tau,
                                                float* __restrict__ out_tau) {
    const int row = blockIdx.x;
    const int tid = threadIdx.x;
    const int warp = tid >> 5, lane = tid & 31;   // warp == head
    const int b = row / TT;

    __shared__ int   sidx[KSEL];
    __shared__ float sbias[KSEL];
    __shared__ float stval[KSEL];
    __shared__ float ssig[KSEL];
    __shared__ float sinv;

    if (tid < KSEL) {
        ull key = g_topkey[row * KSEL + tid];
        int id = 0x7FFFFFFF - (int)(key & 0xFFFFFFFFu);
        float tv = __uint_as_float((unsigned)(key >> 32));
        sidx[tid]  = id;
        stval[tid] = tv;
        sbias[tid] = GAMMA_F * logf(tv + 1e-8f);
        ssig[tid]  = 0.f;
    }
    __syncthreads();

    const float* qp = g_qkv + (size_t)row * C3 + warp * DD;
    const float q0 = qp[lane], q1 = qp[lane + 32];

    float logit[KSEL];
    #pragma unroll
    for (int j = 0; j < KSEL; j++) {
        int s = sidx[j];
        const float* kp = g_qkv + (size_t)(b * TT + s) * C3 + CC + warp * DD;
        float p = q0 * kp[lane] + q1 * kp[lane + 32];
        #pragma unroll
        for (int o = 16; o > 0; o >>= 1) p += __shfl_xor_sync(0xffffffffu, p, o);
        logit[j] = p * 0.125f + sbias[j];
    }
    float m = fmaxf(fmaxf(logit[0], logit[1]), fmaxf(logit[2], logit[3]));
    float e[KSEL], se = 0.f;
    #pragma unroll
    for (int j = 0; j < KSEL; j++) { e[j] = expf(logit[j] - m); se += e[j]; }
    float inv = 1.f / se;
    float w[KSEL];
    #pragma unroll
    for (int j = 0; j < KSEL; j++) w[j] = e[j] * inv;

    float o0 = 0.f, o1 = 0.f;
    #pragma unroll
    for (int j = 0; j < KSEL; j++) {
        const float* vp = g_qkv + (size_t)(b * TT + sidx[j]) * C3 + 2 * CC + warp * DD;
        o0 = fmaf(w[j], vp[lane], o0);
        o1 = fmaf(w[j], vp[lane + 32], o1);
    }
    size_t obase = (size_t)row * KTOT + warp * DD;
    g_ao[obase + lane]      = __float2half(o0);
    g_ao[obase + lane + 32] = __float2half(o1);

    if (lane == 0) {
        #pragma unroll
        for (int j = 0; j < KSEL; j++) atomicAdd(&ssig[j], w[j] * (1.0f / HH));
    }
    __syncthreads();
    if (tid == 0) {
        float rs = g_rowsum[row] * (1.0f - RHO_F);
        #pragma unroll
        for (int j = 0; j < KSEL; j++) { float s = ssig[j]; rs += s * s * s; }
        sinv = 1.f / (rs + 1e-8f);
    }
    __syncthreads();

    // tau_new: re-read tau row, scale + write, then patch
    const float f = (1.0f - RHO_F) * sinv;
    const float4* tin = reinterpret_cast<const float4*>(tau + (size_t)row * TT);
    float4* tout = reinterpret_cast<float4*>(out_tau + (size_t)row * TT);
    #pragma unroll
    for (int t = 0; t < 2; t++) {
        int i = tid + t * 256;
        float4 v = tin[i];
        v.x = fminf(v.x * f, TAUCLIP);
        v.y = fminf(v.y * f, TAUCLIP);
        v.z = fminf(v.z * f, TAUCLIP);
        v.w = fminf(v.w * f, TAUCLIP);
        tout[i] = v;
    }
    __syncthreads();
    if (tid < KSEL) {
        float s = ssig[tid];
        float vv = stval[tid] * (1.0f - RHO_F) + s * s * s;
        out_tau[(size_t)row * TT + sidx[tid]] = fminf(vv * sinv, TAUCLIP);
    }
}

// ===================== launch ===============================================
static cudaStream_t s_side = nullptr;
static cudaEvent_t s_evFork = nullptr, s_evJoin = nullptr;

extern "C" void kernel_launch(void* const* d_in, const int* in_sizes, int n_in,
                              void* d_out, int out_size) {
    const float* x     = (const float*)d_in[0];
    const float* tau   = (const float*)d_in[1];
    const float* Wqkv  = (const float*)d_in[2];
    const float* bqkv  = (const float*)d_in[3];
    const float* Wproj = (const float*)d_in[4];
    const float* bproj = (const float*)d_in[5];

    float* out_main = (float*)d_out;
    float* out_tau  = out_main + (size_t)NROW * CC;

    void *p_qkv, *p_xh, *p_wqt, *p_wpt, *p_ao;
    cudaGetSymbolAddress(&p_qkv, g_qkv);
    cudaGetSymbolAddress(&p_xh, g_x_h);
    cudaGetSymbolAddress(&p_wqt, g_wqt);  cudaGetSymbolAddress(&p_wpt, g_wpt);
    cudaGetSymbolAddress(&p_ao, g_ao);

    cudaFuncSetAttribute(qkv_gemm64, cudaFuncAttributeMaxDynamicSharedMemorySize, QKV_SMEM);
    cudaFuncSetAttribute(proj_gemm64, cudaFuncAttributeMaxDynamicSharedMemorySize, PROJ_SMEM);

    if (s_side == nullptr) {
        cudaStreamCreateWithFlags(&s_side, cudaStreamNonBlocking);
        cudaEventCreateWithFlags(&s_evFork, cudaEventDisableTiming);
        cudaEventCreateWithFlags(&s_evJoin, cudaEventDisableTiming);
    }

    // Fork: topk (depends only on tau) runs concurrently with prep + QKV.
    cudaEventRecord(s_evFork, 0);
    cudaStreamWaitEvent(s_side, s_evFork, 0);
    topk_kernel<<<NROW, 256, 0, s_side>>>(tau);
    cudaEventRecord(s_evJoin, s_side);

    // Main chain: prep -> QKV
    prep_fused<<<3072, 256>>>(x, (__half*)p_xh, Wqkv, (__half*)p_wqt, Wproj, (__half*)p_wpt);
    qkv_gemm64<<<dim3(12, NROW / 64), 256, QKV_SMEM>>>(
        (const __half*)p_xh, (const __half*)p_wqt, bqkv, (float*)p_qkv);

    // Join, then attention + tau_new
    cudaStreamWaitEvent(0, s_evJoin, 0);
    attn_tau<<<NROW, 256>>>(tau, out_tau);

    // proj GEMM (64x64 tiles, 512 CTAs, occ 4)
    proj_gemm64<<<dim3(CC / 64, NROW / 64), 256, PROJ_SMEM>>>(
        (const __half*)p_ao, (const __half*)p_wpt, bproj, out_main);
}